// round 2
// baseline (speedup 1.0000x reference)
#include <cuda_runtime.h>
#include <math.h>

#define N_OBJ 32
#define NG    4960
#define NF    16
#define RD    16
#define BATCH 32
#define NQ    512
#define NCOL  512      // BATCH*NF
#define SPLITK 5
#define KCH   992      // NG / SPLITK
#define BM    64
#define BN    64
#define BK    32

typedef unsigned long long ull;

// ---- device scratch (no allocation allowed) ----
__device__ int   g_idx[NG];                 // packed triples a|b<<8|c<<16
__device__ float g_normw[NQ * NG];          // softmax weights  [q][n]
__device__ float g_R[NG * NCOL];            // rel_conv         [n][b*16+f]
__device__ float g_part[SPLITK * NQ * NCOL];// split-K partials

// ---- packed f32x2 helpers (Blackwell) ----
__device__ __forceinline__ void fma2(ull &acc, ull a, ull b) {
    asm("fma.rn.f32x2 %0, %1, %2, %0;" : "+l"(acc) : "l"(a), "l"(b));
}
__device__ __forceinline__ ull pack2(float lo, float hi) {
    ull r; asm("mov.b64 %0, {%1, %2};" : "=l"(r) : "f"(lo), "f"(hi)); return r;
}
__device__ __forceinline__ float2 unpack2(ull v) {
    float2 r; asm("mov.b64 {%0, %1}, %2;" : "=f"(r.x), "=f"(r.y) : "l"(v)); return r;
}

// ============================================================
// Kernel 0: generate C(32,3) combinations in lexicographic order
// ============================================================
__global__ void idx_kernel() {
    int id = blockIdx.x * blockDim.x + threadIdx.x;
    if (id >= NG) return;
    int n = id, a = 0;
    for (;;) { int c = (31 - a) * (30 - a) / 2; if (n < c) break; n -= c; a++; }
    int b = a + 1;
    for (;;) { int c = 31 - b; if (n < c) break; n -= c; b++; }
    int cc = b + 1 + n;
    g_idx[id] = a | (b << 8) | (cc << 16);
}

__device__ __forceinline__ float softplusf(float x) {
    return fmaxf(x, 0.f) + log1pf(expf(-fabsf(x)));
}

// ============================================================
// Kernel 1: norm_w[q][n] = softmax_n( prod_k softplus(gl[q, idx[n,k]]) )
// One block per query q.
// ============================================================
__global__ void normw_kernel(const float* __restrict__ gl) {
    __shared__ float sp_s[N_OBJ];
    __shared__ float ws[NG];
    __shared__ float red[256];
    int q = blockIdx.x, t = threadIdx.x;
    if (t < N_OBJ) sp_s[t] = softplusf(gl[q * N_OBJ + t]);
    __syncthreads();

    float lmax = -1e30f;
    for (int n = t; n < NG; n += 256) {
        int p = g_idx[n];
        float w = sp_s[p & 255] * sp_s[(p >> 8) & 255] * sp_s[(p >> 16) & 255];
        ws[n] = w;
        lmax = fmaxf(lmax, w);
    }
    red[t] = lmax; __syncthreads();
    for (int s = 128; s > 0; s >>= 1) { if (t < s) red[t] = fmaxf(red[t], red[t + s]); __syncthreads(); }
    float m = red[0]; __syncthreads();

    float lsum = 0.f;
    for (int n = t; n < NG; n += 256) {
        float e = expf(ws[n] - m);   // BETA = 1
        ws[n] = e;
        lsum += e;
    }
    red[t] = lsum; __syncthreads();
    for (int s = 128; s > 0; s >>= 1) { if (t < s) red[t] += red[t + s]; __syncthreads(); }
    float inv = 1.f / red[0];

    for (int n = t; n < NG; n += 256)
        g_normw[q * NG + n] = ws[n] * inv;
}

// ============================================================
// Kernel 2: rel_conv. One block per group n; thread (b = t>>3, fp = t&7)
// computes filters fp and fp+8 for batch b. Output layout R[n][b*16+f].
// ============================================================
__global__ void __launch_bounds__(256) relconv_kernel(
    const float* __restrict__ inp, const float* __restrict__ filt) {
    __shared__ __align__(16) float s_f[NF * 9 * RD];    // 2304 floats
    __shared__ __align__(16) float s_in[BATCH * 9 * RD];// 4608 floats
    int n = blockIdx.x, t = threadIdx.x;

    // stage filters (layout identical to global: [f][ij][d])
    {
        const float4* fsrc = (const float4*)filt;
        float4* fdst = (float4*)s_f;
        for (int i = t; i < 576; i += 256) fdst[i] = fsrc[i];
    }
    int p = g_idx[n];
    int a0 = p & 255, a1 = (p >> 8) & 255, a2 = (p >> 16) & 255;

    // stage the 9 gathered relation vectors for all 32 batches: s_in[b][ij][d]
    {
        const float4* isrc = (const float4*)inp;
        float4* idst = (float4*)s_in;
        for (int u = t; u < 1152; u += 256) {
            int b = u / 36, rm = u % 36, ij = rm >> 2, d4 = rm & 3;
            int ii = ij / 3, jj = ij - ii * 3;
            int ai = (ii == 0) ? a0 : ((ii == 1) ? a1 : a2);
            int aj = (jj == 0) ? a0 : ((jj == 1) ? a1 : a2);
            idst[u] = isrc[((b * N_OBJ + ai) * N_OBJ + aj) * 4 + d4];
        }
    }
    __syncthreads();

    int b = t >> 3, fp = t & 7;
    const ulonglong2* in2 = (const ulonglong2*)s_in;  // [BATCH][36]
    const ulonglong2* f2  = (const ulonglong2*)s_f;   // [NF][36]
    ull a0a = 0, a0b = 0, a1a = 0, a1b = 0;
    #pragma unroll
    for (int m = 0; m < 36; m++) {
        ulonglong2 vi = in2[b * 36 + m];
        ulonglong2 v0 = f2[fp * 36 + m];
        ulonglong2 v1 = f2[(fp + 8) * 36 + m];
        fma2(a0a, vi.x, v0.x); fma2(a0b, vi.y, v0.y);
        fma2(a1a, vi.x, v1.x); fma2(a1b, vi.y, v1.y);
    }
    float2 r0a = unpack2(a0a), r0b = unpack2(a0b);
    float2 r1a = unpack2(a1a), r1b = unpack2(a1b);
    g_R[n * NCOL + b * NF + fp]     = r0a.x + r0a.y + r0b.x + r0b.y;
    g_R[n * NCOL + b * NF + fp + 8] = r1a.x + r1a.y + r1b.x + r1b.y;
}

// ============================================================
// Kernel 3: split-K GEMM  part[z][q][col] = sum_{k in chunk z} W[q,k]*R[k,col]
// 64x64 tile, BK=32, 256 threads, 4x4 outputs/thread, f32x2 accumulate.
// grid = (8 colTiles, 8 qTiles, 5 splits)
// ============================================================
__global__ void __launch_bounds__(256) gemm_kernel() {
    __shared__ ull Ws2[BK][BM + 1];              // (w,w) duplicated, padded
    __shared__ __align__(16) float Rs[BK][BN];
    int t = threadIdx.x;
    int tx = t & 15, ty = t >> 4;
    int colBase = blockIdx.x * BN;
    int qBase   = blockIdx.y * BM;
    int z       = blockIdx.z;
    int kBase   = z * KCH;

    ull acc[4][2];
    #pragma unroll
    for (int i = 0; i < 4; i++) { acc[i][0] = 0ull; acc[i][1] = 0ull; }

    for (int kt = 0; kt < KCH / BK; kt++) {
        int kOff = kBase + kt * BK;
        // load W tile 64q x 32k, store duplicated as f32x2 in [k][q]
        {
            int row = t >> 3, c4 = (t & 7) * 4;
            #pragma unroll
            for (int rr = 0; rr < 2; rr++) {
                int qq = row + rr * 32;
                float4 v = *(const float4*)&g_normw[(qBase + qq) * NG + kOff + c4];
                Ws2[c4 + 0][qq] = pack2(v.x, v.x);
                Ws2[c4 + 1][qq] = pack2(v.y, v.y);
                Ws2[c4 + 2][qq] = pack2(v.z, v.z);
                Ws2[c4 + 3][qq] = pack2(v.w, v.w);
            }
        }
        // load R tile 32k x 64col
        {
            int row = t >> 4, c4 = (t & 15) * 4;
            #pragma unroll
            for (int rr = 0; rr < 2; rr++) {
                int kk = row + rr * 16;
                *(float4*)&Rs[kk][c4] = *(const float4*)&g_R[(kOff + kk) * NCOL + colBase + c4];
            }
        }
        __syncthreads();
        #pragma unroll
        for (int kk = 0; kk < BK; kk++) {
            const ull* rrow = (const ull*)&Rs[kk][0];
            ull r0 = rrow[tx * 2], r1 = rrow[tx * 2 + 1];
            ull w0 = Ws2[kk][ty * 4 + 0];
            ull w1 = Ws2[kk][ty * 4 + 1];
            ull w2 = Ws2[kk][ty * 4 + 2];
            ull w3 = Ws2[kk][ty * 4 + 3];
            fma2(acc[0][0], w0, r0); fma2(acc[0][1], w0, r1);
            fma2(acc[1][0], w1, r0); fma2(acc[1][1], w1, r1);
            fma2(acc[2][0], w2, r0); fma2(acc[2][1], w2, r1);
            fma2(acc[3][0], w3, r0); fma2(acc[3][1], w3, r1);
        }
        __syncthreads();
    }
    #pragma unroll
    for (int i = 0; i < 4; i++) {
        float2 lo = unpack2(acc[i][0]);
        float2 hi = unpack2(acc[i][1]);
        float4 v = make_float4(lo.x, lo.y, hi.x, hi.y);
        int q = qBase + ty * 4 + i;
        *(float4*)&g_part[(z * NQ + q) * NCOL + colBase + tx * 4] = v;
    }
}

// ============================================================
// Kernel 4: split-K reduce + scatter to output layout out[b][q][f]
// ============================================================
__global__ void reduce_kernel(float* __restrict__ out) {
    int tid = blockIdx.x * blockDim.x + threadIdx.x; // 262144 total
    int q = tid >> 9, col = tid & 511;
    float s = 0.f;
    #pragma unroll
    for (int zz = 0; zz < SPLITK; zz++) s += g_part[(zz * NQ + q) * NCOL + col];
    out[(col >> 4) * (NQ * NF) + q * NF + (col & 15)] = s;
}

extern "C" void kernel_launch(void* const* d_in, const int* in_sizes, int n_in,
                              void* d_out, int out_size) {
    const float* inputs = (const float*)d_in[0];
    const float* gl     = (const float*)d_in[1];
    const float* filt   = (const float*)d_in[2];
    float* out = (float*)d_out;

    idx_kernel<<<20, 256>>>();
    normw_kernel<<<NQ, 256>>>(gl);
    relconv_kernel<<<NG, 256>>>(inputs, filt);
    gemm_kernel<<<dim3(NCOL / BN, NQ / BM, SPLITK), 256>>>();
    reduce_kernel<<<NQ, 512>>>(out);
}

// round 4
// speedup vs baseline: 2.0078x; 2.0078x over previous
#include <cuda_runtime.h>
#include <math.h>

#define N_OBJ 32
#define NG    4960
#define NF    16
#define RD    16
#define BATCH 32
#define NQ    512
#define NCOL  512      // BATCH*NF
#define SPLITK 10
#define KCH   496      // NG / SPLITK
#define BM    64
#define BN    64
#define BK    16

typedef unsigned long long ull;

// ---- device scratch ----
__device__ int   g_idx[NG];                  // packed triples a|b<<8|c<<16
__device__ float g_normw[NQ * NG];           // softmax weights [q][n]
__device__ ull   g_E[32768 * 9 * 8];         // E[b,a,a'][ij][fp] pairs (f,f+8)  18.9MB
__device__ ull   g_R2[NG * 256];             // R[n][b*8+fp] pairs (f,f+8)       10MB
__device__ float g_part[SPLITK * NQ * NCOL]; // split-K partials                 10MB

// ---- packed f32x2 helpers ----
__device__ __forceinline__ void fma2(ull &acc, ull a, ull b) {
    asm("fma.rn.f32x2 %0, %1, %2, %0;" : "+l"(acc) : "l"(a), "l"(b));
}
__device__ __forceinline__ void add2(ull &acc, ull a) {
    asm("add.rn.f32x2 %0, %0, %1;" : "+l"(acc) : "l"(a));
}
__device__ __forceinline__ ull pack2(float lo, float hi) {
    ull r; asm("mov.b64 %0, {%1, %2};" : "=l"(r) : "f"(lo), "f"(hi)); return r;
}
__device__ __forceinline__ float2 unpack2(ull v) {
    float2 r; asm("mov.b64 {%0, %1}, %2;" : "=f"(r.x), "=f"(r.y) : "l"(v)); return r;
}

// ============================================================
// Kernel 0: generate C(32,3) combinations (lexicographic)
// ============================================================
__global__ void idx_kernel() {
    int id = blockIdx.x * blockDim.x + threadIdx.x;
    if (id >= NG) return;
    int n = id, a = 0;
    for (;;) { int c = (31 - a) * (30 - a) / 2; if (n < c) break; n -= c; a++; }
    int b = a + 1;
    for (;;) { int c = 31 - b; if (n < c) break; n -= c; b++; }
    int cc = b + 1 + n;
    g_idx[id] = a | (b << 8) | (cc << 16);
}

__device__ __forceinline__ float softplusf(float x) {
    return fmaxf(x, 0.f) + log1pf(__expf(-fabsf(x)));
}

// ============================================================
// Kernel 1: norm_w[q][n] = softmax_n( prod softplus(gl[q, idx[n,:]]) )
// ============================================================
__global__ void __launch_bounds__(256) normw_kernel(const float* __restrict__ gl) {
    __shared__ float sp_s[N_OBJ];
    __shared__ float ws[NG];
    __shared__ float red[8];
    int q = blockIdx.x, t = threadIdx.x;
    int lane = t & 31, warp = t >> 5;
    if (t < N_OBJ) sp_s[t] = softplusf(gl[q * N_OBJ + t]);
    __syncthreads();

    float lmax = -1e30f;
    for (int n = t; n < NG; n += 256) {
        int p = g_idx[n];
        float w = sp_s[p & 255] * sp_s[(p >> 8) & 255] * sp_s[(p >> 16) & 255];
        ws[n] = w;
        lmax = fmaxf(lmax, w);
    }
    #pragma unroll
    for (int o = 16; o; o >>= 1) lmax = fmaxf(lmax, __shfl_xor_sync(0xffffffffu, lmax, o));
    if (lane == 0) red[warp] = lmax;
    __syncthreads();
    float m = red[0];
    #pragma unroll
    for (int i = 1; i < 8; i++) m = fmaxf(m, red[i]);
    __syncthreads();

    float lsum = 0.f;
    for (int n = t; n < NG; n += 256) {
        float e = __expf(ws[n] - m);   // BETA = 1
        ws[n] = e;
        lsum += e;
    }
    #pragma unroll
    for (int o = 16; o; o >>= 1) lsum += __shfl_xor_sync(0xffffffffu, lsum, o);
    if (lane == 0) red[warp] = lsum;
    __syncthreads();
    float s = red[0];
    #pragma unroll
    for (int i = 1; i < 8; i++) s += red[i];
    float inv = 1.f / s;

    for (int n = t; n < NG; n += 256)
        g_normw[q * NG + n] = ws[n] * inv;
}

// ============================================================
// Kernel 2a: E[b,a,a'][ij][fp] = pack( sum_d inp[b,a,a',d]*filt[fp,ij,d],
//                                      sum_d inp[b,a,a',d]*filt[fp+8,ij,d] )
// Dense GEMM, 75 MMAC. One thread per (b,a,a') row; 256 blocks x 128 thr.
// ============================================================
__global__ void __launch_bounds__(128) eproj_kernel(
    const float* __restrict__ inp, const float* __restrict__ filt) {
    __shared__ ull s_ft[9 * 16 * 8];   // [ij][d][fp] pairs (f,f+8)
    int t = threadIdx.x;
    for (int u = t; u < 1152; u += 128) {
        int fp = u & 7, d = (u >> 3) & 15, ij = u >> 7;
        s_ft[u] = pack2(filt[fp * 144 + ij * 16 + d],
                        filt[(fp + 8) * 144 + ij * 16 + d]);
    }
    __syncthreads();

    int row = blockIdx.x * 128 + t;        // (b*32+a)*32+a'
    // load the 16-float relation vector, pre-duplicate into f32x2
    ull s2[16];
    {
        const float4* src = (const float4*)(inp + row * RD);
        #pragma unroll
        for (int i = 0; i < 4; i++) {
            float4 v = src[i];
            s2[i * 4 + 0] = pack2(v.x, v.x);
            s2[i * 4 + 1] = pack2(v.y, v.y);
            s2[i * 4 + 2] = pack2(v.z, v.z);
            s2[i * 4 + 3] = pack2(v.w, v.w);
        }
    }
    #pragma unroll
    for (int ij = 0; ij < 9; ij++) {
        ull acc[8];
        #pragma unroll
        for (int f = 0; f < 8; f++) acc[f] = 0ull;
        #pragma unroll
        for (int d = 0; d < 16; d++) {
            const ull* fr = &s_ft[(ij * 16 + d) * 8];
            #pragma unroll
            for (int f = 0; f < 8; f++) fma2(acc[f], s2[d], fr[f]);
        }
        ull* dst = &g_E[(row * 9 + ij) * 8];
        #pragma unroll
        for (int f = 0; f < 8; f++) dst[f] = acc[f];
    }
}

// ============================================================
// Kernel 2b: R[n][b*8+fp] = sum_{ij} E[(b,a_i,a_j)][ij][fp]
// 620 blocks x 8 groups each, 256 threads: t -> (b = t>>3, fp = t&7)
// ============================================================
__global__ void __launch_bounds__(256) assemble_kernel() {
    int t = threadIdx.x;
    int b = t >> 3, fp = t & 7;
    #pragma unroll
    for (int g = 0; g < 8; g++) {
        int n = blockIdx.x * 8 + g;
        int p = g_idx[n];
        int o0 = p & 255, o1 = (p >> 8) & 255, o2 = (p >> 16) & 255;
        int objs[3] = {o0, o1, o2};
        ull acc = 0ull;
        #pragma unroll
        for (int ij = 0; ij < 9; ij++) {
            int ii = ij / 3, jj = ij - ii * 3;
            int row = (b * 32 + objs[ii]) * 32 + objs[jj];
            add2(acc, g_E[(row * 9 + ij) * 8 + fp]);
        }
        g_R2[n * 256 + t] = acc;
    }
}

// ============================================================
// Kernel 3: split-K GEMM  part[z][q][col'] = sum_k W[q,k]*R[k,col']
// col' = b*16 + fp*2 + sel  (pair layout). 64x64 tile, BK=16, 256 thr.
// grid = (8, 8, SPLITK=10) = 640 blocks.
// ============================================================
__global__ void __launch_bounds__(256) gemm_kernel() {
    __shared__ ull Ws2[BK][BM + 1];
    __shared__ __align__(16) float Rs[BK][BN];
    const float* Rf = (const float*)g_R2;
    int t = threadIdx.x;
    int tx = t & 15, ty = t >> 4;
    int colBase = blockIdx.x * BN;
    int qBase   = blockIdx.y * BM;
    int kBase   = blockIdx.z * KCH;

    ull acc[4][2];
    #pragma unroll
    for (int i = 0; i < 4; i++) { acc[i][0] = 0ull; acc[i][1] = 0ull; }

    for (int kt = 0; kt < KCH / BK; kt++) {
        int kOff = kBase + kt * BK;
        // W tile 64q x 16k -> duplicated f32x2 [k][q]
        {
            int row = t >> 2, c4 = (t & 3) * 4;
            float4 v = *(const float4*)&g_normw[(qBase + row) * NG + kOff + c4];
            Ws2[c4 + 0][row] = pack2(v.x, v.x);
            Ws2[c4 + 1][row] = pack2(v.y, v.y);
            Ws2[c4 + 2][row] = pack2(v.z, v.z);
            Ws2[c4 + 3][row] = pack2(v.w, v.w);
        }
        // R tile 16k x 64col
        {
            int row = t >> 4, c4 = (t & 15) * 4;
            *(float4*)&Rs[row][c4] = *(const float4*)&Rf[(kOff + row) * NCOL + colBase + c4];
        }
        __syncthreads();
        #pragma unroll
        for (int kk = 0; kk < BK; kk++) {
            const ull* rrow = (const ull*)&Rs[kk][0];
            ull r0 = rrow[tx * 2], r1 = rrow[tx * 2 + 1];
            ull w0 = Ws2[kk][ty * 4 + 0];
            ull w1 = Ws2[kk][ty * 4 + 1];
            ull w2 = Ws2[kk][ty * 4 + 2];
            ull w3 = Ws2[kk][ty * 4 + 3];
            fma2(acc[0][0], w0, r0); fma2(acc[0][1], w0, r1);
            fma2(acc[1][0], w1, r0); fma2(acc[1][1], w1, r1);
            fma2(acc[2][0], w2, r0); fma2(acc[2][1], w2, r1);
            fma2(acc[3][0], w3, r0); fma2(acc[3][1], w3, r1);
        }
        __syncthreads();
    }
    #pragma unroll
    for (int i = 0; i < 4; i++) {
        float2 lo = unpack2(acc[i][0]);
        float2 hi = unpack2(acc[i][1]);
        float4 v = make_float4(lo.x, lo.y, hi.x, hi.y);
        int q = qBase + ty * 4 + i;
        *(float4*)&g_part[(blockIdx.z * NQ + q) * NCOL + colBase + tx * 4] = v;
    }
}

// ============================================================
// Kernel 4: split-K reduce + unmap col' -> (b,f), out[b][q][f]
// ============================================================
__global__ void reduce_kernel(float* __restrict__ out) {
    int tid = blockIdx.x * blockDim.x + threadIdx.x;  // 262144
    int q = tid >> 9, col = tid & 511;
    float s = 0.f;
    #pragma unroll
    for (int z = 0; z < SPLITK; z++) s += g_part[(z * NQ + q) * NCOL + col];
    int b = col >> 4;
    int f = ((col >> 1) & 7) + ((col & 1) << 3);
    out[b * (NQ * NF) + q * NF + f] = s;
}

extern "C" void kernel_launch(void* const* d_in, const int* in_sizes, int n_in,
                              void* d_out, int out_size) {
    const float* inputs = (const float*)d_in[0];
    const float* gl     = (const float*)d_in[1];
    const float* filt   = (const float*)d_in[2];
    float* out = (float*)d_out;

    idx_kernel<<<20, 256>>>();
    normw_kernel<<<NQ, 256>>>(gl);
    eproj_kernel<<<256, 128>>>(inputs, filt);
    assemble_kernel<<<620, 256>>>();
    gemm_kernel<<<dim3(NCOL / BN, NQ / BM, SPLITK), 256>>>();
    reduce_kernel<<<NQ, 512>>>(out);
}

// round 9
// speedup vs baseline: 3.2916x; 1.6394x over previous
#include <cuda_runtime.h>
#include <cuda_bf16.h>
#include <math.h>
#include <stdint.h>

#define N_OBJ 32
#define NG    4960
#define NGP   5120      // padded K (zero tail)
#define NF    16
#define RD    16
#define BATCH 32
#define NQ    512
#define NCOL  512       // BATCH*NF
#define SPLITK 10
#define KSP   512       // NGP / SPLITK
#define TK    32        // K per smem stage
#define NSTAGE (KSP/TK) // 16
#define ROWP  40        // padded row stride in bf16 (80B, bank-conflict-free ldmatrix)
#define ARRS  (128*ROWP)  // 5120 bf16 per array
#define BUFS  (4*ARRS)    // Wh,Wl,Rh,Rl per buffer

typedef unsigned long long ull;

// ---- device scratch ----
__device__ int   g_idx[NG];
__device__ ull   g_E[32768 * 9 * 8];            // E[b,a,a'][ij][fp] f32x2 pairs
__device__ __nv_bfloat16 g_Wh[NQ * NGP];        // softmax weights hi  [q][k]
__device__ __nv_bfloat16 g_Wl[NQ * NGP];        // softmax weights lo
__device__ __nv_bfloat16 g_Rh[NCOL * NGP];      // rel_conv hi, TRANSPOSED [col][k]
__device__ __nv_bfloat16 g_Rl[NCOL * NGP];      // rel_conv lo
__device__ float g_part[SPLITK * NQ * NCOL];    // split-K partials

// ---- packed f32x2 helpers ----
__device__ __forceinline__ void fma2(ull &acc, ull a, ull b) {
    asm("fma.rn.f32x2 %0, %1, %2, %0;" : "+l"(acc) : "l"(a), "l"(b));
}
__device__ __forceinline__ void add2(ull &acc, ull a) {
    asm("add.rn.f32x2 %0, %0, %1;" : "+l"(acc) : "l"(a));
}
__device__ __forceinline__ ull pack2(float lo, float hi) {
    ull r; asm("mov.b64 %0, {%1, %2};" : "=l"(r) : "f"(lo), "f"(hi)); return r;
}
__device__ __forceinline__ float2 unpack2(ull v) {
    float2 r; asm("mov.b64 {%0, %1}, %2;" : "=f"(r.x), "=f"(r.y) : "l"(v)); return r;
}
__device__ __forceinline__ uint32_t smem_u32(const void* p) {
    uint32_t a;
    asm("{ .reg .u64 t; cvta.to.shared.u64 t, %1; cvt.u32.u64 %0, t; }" : "=r"(a) : "l"(p));
    return a;
}

#define LDSM_X4(r, addr) \
    asm volatile("ldmatrix.sync.aligned.m8n8.x4.shared.b16 {%0,%1,%2,%3}, [%4];" \
        : "=r"((r)[0]), "=r"((r)[1]), "=r"((r)[2]), "=r"((r)[3]) : "r"(addr))

#define MMA16816(d, a, b0, b1) \
    asm volatile("mma.sync.aligned.m16n8k16.row.col.f32.bf16.bf16.f32 " \
        "{%0,%1,%2,%3},{%4,%5,%6,%7},{%8,%9},{%0,%1,%2,%3};" \
        : "+f"((d)[0]), "+f"((d)[1]), "+f"((d)[2]), "+f"((d)[3]) \
        : "r"((a)[0]), "r"((a)[1]), "r"((a)[2]), "r"((a)[3]), "r"(b0), "r"(b1))

// ============================================================
// Kernel 0: generate C(32,3) combinations (lexicographic)
// ============================================================
__global__ void idx_kernel() {
    int id = blockIdx.x * blockDim.x + threadIdx.x;
    if (id >= NG) return;
    int n = id, a = 0;
    for (;;) { int c = (31 - a) * (30 - a) / 2; if (n < c) break; n -= c; a++; }
    int b = a + 1;
    for (;;) { int c = 31 - b; if (n < c) break; n -= c; b++; }
    int cc = b + 1 + n;
    g_idx[id] = a | (b << 8) | (cc << 16);
}

__device__ __forceinline__ float softplusf(float x) {
    return fmaxf(x, 0.f) + log1pf(__expf(-fabsf(x)));
}

// ============================================================
// Kernel 1: softmax weights -> bf16 hi/lo, K-major, zero-padded tail
// ============================================================
__global__ void __launch_bounds__(256) normw_kernel(const float* __restrict__ gl) {
    __shared__ float sp_s[N_OBJ];
    __shared__ float ws[NG];
    __shared__ float red[8];
    int q = blockIdx.x, t = threadIdx.x;
    int lane = t & 31, warp = t >> 5;
    if (t < N_OBJ) sp_s[t] = softplusf(gl[q * N_OBJ + t]);
    __syncthreads();

    float lmax = -1e30f;
    for (int n = t; n < NG; n += 256) {
        int p = g_idx[n];
        float w = sp_s[p & 255] * sp_s[(p >> 8) & 255] * sp_s[(p >> 16) & 255];
        ws[n] = w;
        lmax = fmaxf(lmax, w);
    }
    #pragma unroll
    for (int o = 16; o; o >>= 1) lmax = fmaxf(lmax, __shfl_xor_sync(0xffffffffu, lmax, o));
    if (lane == 0) red[warp] = lmax;
    __syncthreads();
    float m = red[0];
    #pragma unroll
    for (int i = 1; i < 8; i++) m = fmaxf(m, red[i]);
    __syncthreads();

    float lsum = 0.f;
    for (int n = t; n < NG; n += 256) {
        float e = __expf(ws[n] - m);   // BETA = 1
        ws[n] = e;
        lsum += e;
    }
    #pragma unroll
    for (int o = 16; o; o >>= 1) lsum += __shfl_xor_sync(0xffffffffu, lsum, o);
    if (lane == 0) red[warp] = lsum;
    __syncthreads();
    float s = red[0];
    #pragma unroll
    for (int i = 1; i < 8; i++) s += red[i];
    float inv = 1.f / s;

    for (int n = t; n < NGP; n += 256) {
        float w = (n < NG) ? ws[n] * inv : 0.f;
        __nv_bfloat16 h = __float2bfloat16(w);
        float l = w - __bfloat162float(h);
        g_Wh[q * NGP + n] = h;
        g_Wl[q * NGP + n] = __float2bfloat16(l);
    }
}

// ============================================================
// Kernel 2a: E[b,a,a'][ij][fp] = pairs over (f, f+8); dense 75 MMAC
// ============================================================
__global__ void __launch_bounds__(128) eproj_kernel(
    const float* __restrict__ inp, const float* __restrict__ filt) {
    __shared__ ull s_ft[9 * 16 * 8];   // [ij][d][fp] pairs (f,f+8)
    int t = threadIdx.x;
    for (int u = t; u < 1152; u += 128) {
        int fp = u & 7, d = (u >> 3) & 15, ij = u >> 7;
        s_ft[u] = pack2(filt[fp * 144 + ij * 16 + d],
                        filt[(fp + 8) * 144 + ij * 16 + d]);
    }
    __syncthreads();

    int row = blockIdx.x * 128 + t;        // (b*32+a)*32+a'
    ull s2[16];
    {
        const float4* src = (const float4*)(inp + row * RD);
        #pragma unroll
        for (int i = 0; i < 4; i++) {
            float4 v = src[i];
            s2[i * 4 + 0] = pack2(v.x, v.x);
            s2[i * 4 + 1] = pack2(v.y, v.y);
            s2[i * 4 + 2] = pack2(v.z, v.z);
            s2[i * 4 + 3] = pack2(v.w, v.w);
        }
    }
    #pragma unroll
    for (int ij = 0; ij < 9; ij++) {
        ull acc[8];
        #pragma unroll
        for (int f = 0; f < 8; f++) acc[f] = 0ull;
        #pragma unroll
        for (int d = 0; d < 16; d++) {
            const ull* fr = &s_ft[(ij * 16 + d) * 8];
            #pragma unroll
            for (int f = 0; f < 8; f++) fma2(acc[f], s2[d], fr[f]);
        }
        ull* dst = &g_E[(row * 9 + ij) * 8];
        #pragma unroll
        for (int f = 0; f < 8; f++) dst[f] = acc[f];
    }
}

// ============================================================
// Kernel 2b: assemble R, write TRANSPOSED bf16 hi/lo [col][k]
// ============================================================
__global__ void __launch_bounds__(256) assemble_kernel() {
    __shared__ float s_v[8][NCOL];   // [g][col] fp32
    int t = threadIdx.x;
    int b = t >> 3, fp = t & 7;
    int n0 = blockIdx.x * 8;
    #pragma unroll
    for (int g = 0; g < 8; g++) {
        int n = n0 + g;
        float vx = 0.f, vy = 0.f;
        if (n < NG) {
            int p = g_idx[n];
            int o0 = p & 255, o1 = (p >> 8) & 255, o2 = (p >> 16) & 255;
            int objs[3] = {o0, o1, o2};
            ull acc = 0ull;
            #pragma unroll
            for (int ij = 0; ij < 9; ij++) {
                int ii = ij / 3, jj = ij - ii * 3;
                int rw = (b * 32 + objs[ii]) * 32 + objs[jj];
                add2(acc, g_E[(rw * 9 + ij) * 8 + fp]);
            }
            float2 v = unpack2(acc);
            vx = v.x; vy = v.y;
        }
        s_v[g][b * NF + fp]     = vx;   // f = fp
        s_v[g][b * NF + fp + 8] = vy;   // f = fp+8
    }
    __syncthreads();
    for (int c = t; c < NCOL; c += 256) {
        uint32_t uh[4], ul[4];
        #pragma unroll
        for (int p2 = 0; p2 < 4; p2++) {
            uint32_t h2 = 0, l2 = 0;
            #pragma unroll
            for (int e = 0; e < 2; e++) {
                float x = s_v[p2 * 2 + e][c];
                __nv_bfloat16 h = __float2bfloat16(x);
                float l = x - __bfloat162float(h);
                __nv_bfloat16 lb = __float2bfloat16(l);
                h2 |= (uint32_t)__bfloat16_as_ushort(h) << (e * 16);
                l2 |= (uint32_t)__bfloat16_as_ushort(lb) << (e * 16);
            }
            uh[p2] = h2; ul[p2] = l2;
        }
        *(uint4*)&g_Rh[(size_t)c * NGP + n0] = make_uint4(uh[0], uh[1], uh[2], uh[3]);
        *(uint4*)&g_Rl[(size_t)c * NGP + n0] = make_uint4(ul[0], ul[1], ul[2], ul[3]);
    }
}

// ============================================================
// Kernel 3: HMMA bf16-split GEMM via mma.sync m16n8k16.
// CTA 128q x 128col, K stage 32, double-buffered cp.async.
// grid (4 colTiles, 4 qTiles, SPLITK=10) = 160 CTAs.
// ============================================================
__global__ void __launch_bounds__(256) gemm_kernel() {
    extern __shared__ __align__(128) __nv_bfloat16 smem[];  // 2 * BUFS bf16
    const int t = threadIdx.x, lane = t & 31, w = t >> 5;
    const int qBase   = blockIdx.y * 128;
    const int colBase = blockIdx.x * 128;
    const int kBase   = blockIdx.z * KSP;
    const int mrow = (w >> 1) * 32;     // warp m offset within tile
    const int ncol = (w & 1) * 64;      // warp n offset within tile

    float acc[2][8][4];
    #pragma unroll
    for (int i = 0; i < 2; i++)
        #pragma unroll
        for (int j = 0; j < 8; j++)
            #pragma unroll
            for (int k = 0; k < 4; k++) acc[i][j][k] = 0.f;

    // ---- stage loader: 2048 x 16B chunks ----
    auto load_stage = [&](int s, int buf) {
        int kOff = kBase + s * TK;
        __nv_bfloat16* B = smem + buf * BUFS;
        #pragma unroll
        for (int i = 0; i < 8; i++) {
            int c = t + i * 256;               // 0..2047
            int arr = c >> 9;                  // 0:Wh 1:Wl 2:Rh 3:Rl (const per i-pair)
            int r = (c >> 2) & 127, q4 = c & 3;
            const __nv_bfloat16* gsrc;
            if (arr == 0)      gsrc = &g_Wh[(size_t)(qBase + r) * NGP + kOff];
            else if (arr == 1) gsrc = &g_Wl[(size_t)(qBase + r) * NGP + kOff];
            else if (arr == 2) gsrc = &g_Rh[(size_t)(colBase + r) * NGP + kOff];
            else               gsrc = &g_Rl[(size_t)(colBase + r) * NGP + kOff];
            uint32_t sdst = smem_u32(B + arr * ARRS + r * ROWP + q4 * 8);
            asm volatile("cp.async.cg.shared.global [%0], [%1], 16;"
                         :: "r"(sdst), "l"(gsrc + q4 * 8));
        }
        asm volatile("cp.async.commit_group;" ::: "memory");
    };

    load_stage(0, 0);

    for (int s = 0; s < NSTAGE; s++) {
        if (s + 1 < NSTAGE) {
            load_stage(s + 1, (s + 1) & 1);
            asm volatile("cp.async.wait_group 1;" ::: "memory");
        } else {
            asm volatile("cp.async.wait_group 0;" ::: "memory");
        }
        __syncthreads();

        const __nv_bfloat16* B = smem + (s & 1) * BUFS;
        #pragma unroll
        for (int kk = 0; kk < 2; kk++) {
            int koff = kk * 16;
            uint32_t ah[2][4], al[2][4], bh[4][4], bl[4][4];
            #pragma unroll
            for (int mt = 0; mt < 2; mt++) {
                int r = mrow + mt * 16 + (lane & 15);
                int ks = koff + ((lane >> 4) << 3);
                LDSM_X4(ah[mt], smem_u32(B + 0 * ARRS + r * ROWP + ks));
                LDSM_X4(al[mt], smem_u32(B + 1 * ARRS + r * ROWP + ks));
            }
            #pragma unroll
            for (int nt2 = 0; nt2 < 4; nt2++) {
                int n = ncol + nt2 * 16 + (lane & 7) + (((lane >> 4) & 1) << 3);
                int ks = koff + (((lane >> 3) & 1) << 3);
                LDSM_X4(bh[nt2], smem_u32(B + 2 * ARRS + n * ROWP + ks));
                LDSM_X4(bl[nt2], smem_u32(B + 3 * ARRS + n * ROWP + ks));
            }
            #pragma unroll
            for (int mt = 0; mt < 2; mt++)
                #pragma unroll
                for (int nt = 0; nt < 8; nt++) {
                    uint32_t h0 = bh[nt >> 1][(nt & 1) * 2], h1 = bh[nt >> 1][(nt & 1) * 2 + 1];
                    uint32_t l0 = bl[nt >> 1][(nt & 1) * 2], l1 = bl[nt >> 1][(nt & 1) * 2 + 1];
                    MMA16816(acc[mt][nt], ah[mt], h0, h1);
                    MMA16816(acc[mt][nt], ah[mt], l0, l1);
                    MMA16816(acc[mt][nt], al[mt], h0, h1);
                }
        }
        __syncthreads();
    }

    // epilogue: scatter acc to split-K partials
    #pragma unroll
    for (int mt = 0; mt < 2; mt++)
        #pragma unroll
        for (int nt = 0; nt < 8; nt++) {
            int row = qBase + mrow + mt * 16 + (lane >> 2);
            int col = colBase + ncol + nt * 8 + ((lane & 3) << 1);
            float* p = &g_part[((size_t)blockIdx.z * NQ + row) * NCOL + col];
            *(float2*)p = make_float2(acc[mt][nt][0], acc[mt][nt][1]);
            *(float2*)(p + 8 * NCOL) = make_float2(acc[mt][nt][2], acc[mt][nt][3]);
        }
}

// ============================================================
// Kernel 4: split-K reduce (float4), col = b*16+f -> out[b][q][f]
// ============================================================
__global__ void __launch_bounds__(256) reduce_kernel(float* __restrict__ out) {
    int tid = blockIdx.x * blockDim.x + threadIdx.x;  // 65536
    int q = tid >> 7, c4 = (tid & 127) << 2;
    float4 s = make_float4(0.f, 0.f, 0.f, 0.f);
    #pragma unroll
    for (int z = 0; z < SPLITK; z++) {
        float4 v = *(const float4*)&g_part[((size_t)z * NQ + q) * NCOL + c4];
        s.x += v.x; s.y += v.y; s.z += v.z; s.w += v.w;
    }
    int b = c4 >> 4, f = c4 & 15;
    *(float4*)&out[b * (NQ * NF) + q * NF + f] = s;
}

extern "C" void kernel_launch(void* const* d_in, const int* in_sizes, int n_in,
                              void* d_out, int out_size) {
    const float* inputs = (const float*)d_in[0];
    const float* gl     = (const float*)d_in[1];
    const float* filt   = (const float*)d_in[2];
    float* out = (float*)d_out;

    cudaFuncSetAttribute(gemm_kernel, cudaFuncAttributeMaxDynamicSharedMemorySize,
                         2 * BUFS * sizeof(__nv_bfloat16));

    idx_kernel<<<20, 256>>>();
    normw_kernel<<<NQ, 256>>>(gl);
    eproj_kernel<<<256, 128>>>(inputs, filt);
    assemble_kernel<<<640, 256>>>();
    gemm_kernel<<<dim3(4, 4, SPLITK), 256, 2 * BUFS * sizeof(__nv_bfloat16)>>>();
    reduce_kernel<<<256, 256>>>(out);
}